// round 1
// baseline (speedup 1.0000x reference)
#include <cuda_runtime.h>

#define SQ  2048
#define NB  2
#define DM  1024
#define NH  16
#define DKH 64
#define MR  (SQ*NB)   // 4096 rows for [S,B,*] matrices

// ---------------- scratch (device globals: allocation-free) ----------------
__device__ float g_Q[(size_t)NB*NH*SQ*DKH];     // [B,H,S,dk] 16.8 MB
__device__ float g_K[(size_t)NB*NH*SQ*DKH];
__device__ float g_V[(size_t)NB*NH*SQ*DKH];
__device__ float g_P[(size_t)NB*NH*SQ*SQ];      // [B,H,S,S]  536.9 MB
__device__ float g_ctx[(size_t)MR*DM];          // [S,B,D]    16.8 MB

// ============================================================================
// TN SGEMM: C = alpha * A(MxK) * B(NxK)^T, both row-major K-contiguous.
// 128x128 block tile, BK=16, 256 threads, 8x8 per thread, double-buffered smem.
// SCATTER=0: C row-major [M,N] (plus batch stride sC)
// SCATTER=1: scatter n->(h,dk), m->(s,b) into [B,H,S,dk]  (QKV projections)
// ============================================================================
template<int SCATTER>
__global__ void __launch_bounds__(256)
gemm_tn(const float* __restrict__ A, const float* __restrict__ Bm,
        float* __restrict__ C, int K, int N, float alpha,
        size_t sA, size_t sB, size_t sC)
{
    __shared__ __align__(16) float As[2][16][132];
    __shared__ __align__(16) float Bs[2][16][132];

    const int t  = threadIdx.x;
    const int z  = blockIdx.z;
    A  += (size_t)z * sA;
    Bm += (size_t)z * sB;
    C  += (size_t)z * sC;

    const int m0 = blockIdx.y * 128;
    const int n0 = blockIdx.x * 128;
    const int lrow = t >> 1;          // 0..127 tile row loaded by this thread
    const int lc8  = (t & 1) * 8;     // 0 or 8: which 8 k's of the 16-wide tile
    const int ty   = t >> 4;          // 0..15 -> output rows ty*8..+7
    const int tx   = t & 15;          // 0..15 -> output cols tx*8..+7

    const float* Ag = A  + (size_t)(m0 + lrow) * K + lc8;
    const float* Bg = Bm + (size_t)(n0 + lrow) * K + lc8;

    float acc[8][8];
    #pragma unroll
    for (int i = 0; i < 8; i++)
        #pragma unroll
        for (int j = 0; j < 8; j++) acc[i][j] = 0.f;

    const int nk = K >> 4;

    // prologue: tile 0 -> buffer 0
    {
        float4 a0 = *(const float4*)(Ag + 0);
        float4 a1 = *(const float4*)(Ag + 4);
        float4 b0 = *(const float4*)(Bg + 0);
        float4 b1 = *(const float4*)(Bg + 4);
        #pragma unroll
        for (int j = 0; j < 4; j++) {
            As[0][lc8 + j    ][lrow] = ((const float*)&a0)[j];
            As[0][lc8 + 4 + j][lrow] = ((const float*)&a1)[j];
            Bs[0][lc8 + j    ][lrow] = ((const float*)&b0)[j];
            Bs[0][lc8 + 4 + j][lrow] = ((const float*)&b1)[j];
        }
    }
    __syncthreads();

    for (int kt = 0; kt < nk; kt++) {
        const int  cur = kt & 1;
        const bool hasnext = (kt + 1 < nk);
        float4 a0, a1, b0, b1;
        if (hasnext) {
            const float* ap = Ag + (kt + 1) * 16;
            const float* bp = Bg + (kt + 1) * 16;
            a0 = *(const float4*)(ap);
            a1 = *(const float4*)(ap + 4);
            b0 = *(const float4*)(bp);
            b1 = *(const float4*)(bp + 4);
        }
        #pragma unroll
        for (int k = 0; k < 16; k++) {
            float4 xa0 = *(const float4*)&As[cur][k][ty * 8];
            float4 xa1 = *(const float4*)&As[cur][k][ty * 8 + 4];
            float4 xb0 = *(const float4*)&Bs[cur][k][tx * 8];
            float4 xb1 = *(const float4*)&Bs[cur][k][tx * 8 + 4];
            float av[8] = {xa0.x, xa0.y, xa0.z, xa0.w, xa1.x, xa1.y, xa1.z, xa1.w};
            float bv[8] = {xb0.x, xb0.y, xb0.z, xb0.w, xb1.x, xb1.y, xb1.z, xb1.w};
            #pragma unroll
            for (int i = 0; i < 8; i++)
                #pragma unroll
                for (int j = 0; j < 8; j++)
                    acc[i][j] = fmaf(av[i], bv[j], acc[i][j]);
        }
        if (hasnext) {
            const int nb2 = cur ^ 1;
            #pragma unroll
            for (int j = 0; j < 4; j++) {
                As[nb2][lc8 + j    ][lrow] = ((const float*)&a0)[j];
                As[nb2][lc8 + 4 + j][lrow] = ((const float*)&a1)[j];
                Bs[nb2][lc8 + j    ][lrow] = ((const float*)&b0)[j];
                Bs[nb2][lc8 + 4 + j][lrow] = ((const float*)&b1)[j];
            }
        }
        __syncthreads();
    }

    // epilogue
    if (SCATTER == 0) {
        #pragma unroll
        for (int i = 0; i < 8; i++) {
            const int m = m0 + ty * 8 + i;
            float* cp = C + (size_t)m * N + n0 + tx * 8;
            float4 r0, r1;
            r0.x = acc[i][0]*alpha; r0.y = acc[i][1]*alpha;
            r0.z = acc[i][2]*alpha; r0.w = acc[i][3]*alpha;
            r1.x = acc[i][4]*alpha; r1.y = acc[i][5]*alpha;
            r1.z = acc[i][6]*alpha; r1.w = acc[i][7]*alpha;
            *(float4*)(cp)     = r0;
            *(float4*)(cp + 4) = r1;
        }
    } else {
        // n -> (h, dk), m -> (s, b); write to [B,H,S,dk]
        const int n  = n0 + tx * 8;
        const int h  = n >> 6;
        const int dk = n & 63;
        #pragma unroll
        for (int i = 0; i < 8; i++) {
            const int m = m0 + ty * 8 + i;
            const int s = m >> 1;
            const int b = m & 1;
            float* cp = C + (((size_t)(b * NH + h) * SQ + s) * DKH + dk);
            float4 r0, r1;
            r0.x = acc[i][0]*alpha; r0.y = acc[i][1]*alpha;
            r0.z = acc[i][2]*alpha; r0.w = acc[i][3]*alpha;
            r1.x = acc[i][4]*alpha; r1.y = acc[i][5]*alpha;
            r1.z = acc[i][6]*alpha; r1.w = acc[i][7]*alpha;
            *(float4*)(cp)     = r0;
            *(float4*)(cp + 4) = r1;
        }
    }
}

// ============================================================================
// Row softmax in-place over last dim (SQ=2048). One block (256 thr) per row.
// ============================================================================
__global__ void __launch_bounds__(256)
softmax_kernel(float* __restrict__ P)
{
    const size_t base = (size_t)blockIdx.x * SQ;
    const int t = threadIdx.x;
    float v[8];
    float mx = -3.4e38f;
    #pragma unroll
    for (int i = 0; i < 8; i++) {
        v[i] = P[base + t + i * 256];
        mx = fmaxf(mx, v[i]);
    }
    __shared__ float red[256];
    red[t] = mx;
    __syncthreads();
    #pragma unroll
    for (int s2 = 128; s2 > 0; s2 >>= 1) {
        if (t < s2) red[t] = fmaxf(red[t], red[t + s2]);
        __syncthreads();
    }
    mx = red[0];
    __syncthreads();
    float sum = 0.f;
    #pragma unroll
    for (int i = 0; i < 8; i++) {
        v[i] = __expf(v[i] - mx);
        sum += v[i];
    }
    red[t] = sum;
    __syncthreads();
    #pragma unroll
    for (int s2 = 128; s2 > 0; s2 >>= 1) {
        if (t < s2) red[t] += red[t + s2];
        __syncthreads();
    }
    const float inv = 1.0f / red[0];
    #pragma unroll
    for (int i = 0; i < 8; i++)
        P[base + t + i * 256] = v[i] * inv;
}

// ============================================================================
// ctx = P(SxS) @ V(Sxdk) per (b,h); writes ctx as [S,B,D] at [s][b][h*64+dk].
// 128x64 block tile, BK=16, 256 threads, 8x4 per thread, double buffered.
// ============================================================================
__global__ void __launch_bounds__(256)
pv_gemm(const float* __restrict__ P, const float* __restrict__ V,
        float* __restrict__ C)
{
    __shared__ __align__(16) float Ps[2][16][132];
    __shared__ __align__(16) float Vs[2][16][64];

    const int t = threadIdx.x;
    const int z = blockIdx.z;
    const int b = z >> 4;
    const int h = z & 15;
    P += (size_t)z * SQ * SQ;
    V += (size_t)z * SQ * DKH;

    const int q0   = blockIdx.y * 128;
    const int lrow = t >> 1;
    const int lc8  = (t & 1) * 8;
    const int vrow = t >> 4;          // 0..15 (k row of V tile)
    const int vc4  = (t & 15) * 4;    // 0..60
    const int ty   = t >> 4;          // output rows ty*8..+7
    const int tx   = t & 15;          // output cols tx*4..+3

    const float* Pg = P + (size_t)(q0 + lrow) * SQ + lc8;
    const float* Vg = V + (size_t)vrow * DKH + vc4;

    float acc[8][4];
    #pragma unroll
    for (int i = 0; i < 8; i++)
        #pragma unroll
        for (int j = 0; j < 4; j++) acc[i][j] = 0.f;

    const int nk = SQ >> 4;   // 128 k-tiles

    {
        float4 a0 = *(const float4*)(Pg + 0);
        float4 a1 = *(const float4*)(Pg + 4);
        float4 v0 = *(const float4*)(Vg);
        #pragma unroll
        for (int j = 0; j < 4; j++) {
            Ps[0][lc8 + j    ][lrow] = ((const float*)&a0)[j];
            Ps[0][lc8 + 4 + j][lrow] = ((const float*)&a1)[j];
        }
        *(float4*)&Vs[0][vrow][vc4] = v0;
    }
    __syncthreads();

    for (int kt = 0; kt < nk; kt++) {
        const int  cur = kt & 1;
        const bool hasnext = (kt + 1 < nk);
        float4 a0, a1, v0;
        if (hasnext) {
            const float* ap = Pg + (kt + 1) * 16;
            const float* vp = Vg + (size_t)(kt + 1) * 16 * DKH;
            a0 = *(const float4*)(ap);
            a1 = *(const float4*)(ap + 4);
            v0 = *(const float4*)(vp);
        }
        #pragma unroll
        for (int k = 0; k < 16; k++) {
            float4 xa0 = *(const float4*)&Ps[cur][k][ty * 8];
            float4 xa1 = *(const float4*)&Ps[cur][k][ty * 8 + 4];
            float4 xb  = *(const float4*)&Vs[cur][k][tx * 4];
            float av[8] = {xa0.x, xa0.y, xa0.z, xa0.w, xa1.x, xa1.y, xa1.z, xa1.w};
            float bv[4] = {xb.x, xb.y, xb.z, xb.w};
            #pragma unroll
            for (int i = 0; i < 8; i++)
                #pragma unroll
                for (int j = 0; j < 4; j++)
                    acc[i][j] = fmaf(av[i], bv[j], acc[i][j]);
        }
        if (hasnext) {
            const int nb2 = cur ^ 1;
            #pragma unroll
            for (int j = 0; j < 4; j++) {
                Ps[nb2][lc8 + j    ][lrow] = ((const float*)&a0)[j];
                Ps[nb2][lc8 + 4 + j][lrow] = ((const float*)&a1)[j];
            }
            *(float4*)&Vs[nb2][vrow][vc4] = v0;
        }
        __syncthreads();
    }

    #pragma unroll
    for (int i = 0; i < 8; i++) {
        const int q = q0 + ty * 8 + i;
        float4 r;
        r.x = acc[i][0]; r.y = acc[i][1]; r.z = acc[i][2]; r.w = acc[i][3];
        *(float4*)(C + ((size_t)q * NB + b) * DM + h * DKH + tx * 4) = r;
    }
}

// ============================================================================
// mean over heads: out[b,q,k] = (1/H) * sum_h P[b,h,q,k]. One block per (b,q).
// ============================================================================
__global__ void __launch_bounds__(256)
mean_kernel(const float* __restrict__ P, float* __restrict__ outMean)
{
    const int bq = blockIdx.x;       // 0 .. NB*SQ-1
    const int b  = bq >> 11;         // / SQ
    const int q  = bq & (SQ - 1);
    const int t  = threadIdx.x;
    float acc[8];
    #pragma unroll
    for (int i = 0; i < 8; i++) acc[i] = 0.f;
    for (int h = 0; h < NH; h++) {
        const float* p = P + (((size_t)(b * NH + h) * SQ + q) * SQ);
        #pragma unroll
        for (int i = 0; i < 8; i++) acc[i] += p[t + i * 256];
    }
    float* o = outMean + (size_t)bq * SQ;
    #pragma unroll
    for (int i = 0; i < 8; i++) o[t + i * 256] = acc[i] * (1.0f / NH);
}

// ============================================================================
extern "C" void kernel_launch(void* const* d_in, const int* in_sizes, int n_in,
                              void* d_out, int out_size)
{
    (void)in_sizes; (void)n_in; (void)out_size;
    const float* q  = (const float*)d_in[0];
    const float* k  = (const float*)d_in[1];
    const float* v  = (const float*)d_in[2];
    const float* Wq = (const float*)d_in[3];
    const float* Wk = (const float*)d_in[4];
    const float* Wv = (const float*)d_in[5];
    const float* Wo = (const float*)d_in[6];
    float* out     = (float*)d_out;
    float* outMean = out + (size_t)MR * DM;

    void *pQ, *pK, *pV, *pP, *pC;
    cudaGetSymbolAddress(&pQ, g_Q);
    cudaGetSymbolAddress(&pK, g_K);
    cudaGetSymbolAddress(&pV, g_V);
    cudaGetSymbolAddress(&pP, g_P);
    cudaGetSymbolAddress(&pC, g_ctx);

    const dim3 thr(256);

    // 1) QKV projections: [4096,1024] x [1024,1024]^T -> scatter [B,H,S,dk]
    const dim3 gproj(DM / 128, MR / 128, 1);
    gemm_tn<1><<<gproj, thr>>>(q, Wq, (float*)pQ, DM, DM, 1.0f, 0, 0, 0);
    gemm_tn<1><<<gproj, thr>>>(k, Wk, (float*)pK, DM, DM, 1.0f, 0, 0, 0);
    gemm_tn<1><<<gproj, thr>>>(v, Wv, (float*)pV, DM, DM, 1.0f, 0, 0, 0);

    // 2) scores: per (b,h)  P = (Q K^T) / sqrt(dk)
    const dim3 gsc(SQ / 128, SQ / 128, NB * NH);
    gemm_tn<0><<<gsc, thr>>>((const float*)pQ, (const float*)pK, (float*)pP,
                             DKH, SQ, 0.125f,
                             (size_t)SQ * DKH, (size_t)SQ * DKH,
                             (size_t)SQ * SQ);

    // 3) softmax rows in place
    softmax_kernel<<<NB * NH * SQ, thr>>>((float*)pP);

    // 4) ctx = P @ V  -> [S,B,D]
    const dim3 gpv(1, SQ / 128, NB * NH);
    pv_gemm<<<gpv, thr>>>((const float*)pP, (const float*)pV, (float*)pC);

    // 5) mean over heads -> second output region
    mean_kernel<<<NB * SQ, thr>>>((const float*)pP, outMean);

    // 6) out = ctx @ Wo^T  -> [S,B,D] row-major == [4096,1024]
    gemm_tn<0><<<gproj, thr>>>((const float*)pC, Wo, out, DM, DM, 1.0f, 0, 0, 0);
}